// round 15
// baseline (speedup 1.0000x reference)
#include <cuda_runtime.h>
#include <cuda_fp16.h>
#include <cstdint>

// ---------------------------------------------------------------- problem dims
constexpr int N_IN  = 32;
constexpr int H_IN  = 56;
constexpr int W_IN  = 56;
constexpr int C_IN  = 256;
constexpr int KH    = 3;
constexpr int KW    = 3;
constexpr int OC    = 256;
constexpr int OH    = 54;
constexpr int OW    = 54;

constexpr int M_TOTAL = N_IN * OH * OW;   // 93312
constexpr int K_TOTAL = KH * KW * C_IN;   // 2304
constexpr float SPARSE_TH = 0.01f;

// ---------------------------------------------------------------- GEMM config
constexpr int BM = 128;
constexpr int BN = 128;
constexpr int BK = 64;                       // 64 fp16 = 128B/row (SW128)
constexpr int NUM_CHUNKS = K_TOTAL / BK;     // 36
constexpr int X_ELEMS = N_IN * H_IN * W_IN * C_IN;  // 25690112

constexpr int THREADS = 128;                 // 4 warps, 2(M) x 2(N), warp tile 64x64

// smem: 2 stages, each A(16KB)+B(16KB) -> 64KB/CTA, 3 CTAs/SM
constexpr int A_CHUNK_BYTES = 16384;
constexpr int STAGE_BYTES   = 32768;
constexpr int SMEM_BYTES    = 2 * STAGE_BYTES;   // 65536

// fp16 image of x
__device__ __half g_xh[X_ELEMS];
// B pre-packed, conflict-free smem order:
// [ck][ntile 0..31][s2 0..1][s1 0..1][lane 0..31][r 0..1] (uint32 words)
// word(tid), tid = s2*128 + s1*64 + lane*2 + r
// word = half2 { B(k), B(k+1) }, k = ck*64 + (s2*2+s1)*16 + r*8 + t*2, n = ntile*8 + g
__device__ uint32_t g_Bpack[NUM_CHUNKS * 32 * 256];

// merged prep grid split
constexpr int PREP_X_BLOCKS = X_ELEMS / 8 / 256;   // 12544 (32B/thread, exact)
constexpr int PREP_B_BLOCKS = NUM_CHUNKS * 32;     // 1152
constexpr int PREP_BLOCKS   = PREP_X_BLOCKS + PREP_B_BLOCKS;

__device__ __forceinline__ uint32_t smem_u32(const void* p) {
    uint32_t a;
    asm("{ .reg .u64 t; cvta.to.shared.u64 t, %1; cvt.u32.u64 %0, t; }" : "=r"(a) : "l"(p));
    return a;
}

__device__ __forceinline__ void mma_f16(float* c, const uint32_t* a, const uint32_t* b) {
    asm volatile(
        "mma.sync.aligned.m16n8k16.row.col.f32.f16.f16.f32 "
        "{%0,%1,%2,%3}, {%4,%5,%6,%7}, {%8,%9}, {%0,%1,%2,%3};"
        : "+f"(c[0]), "+f"(c[1]), "+f"(c[2]), "+f"(c[3])
        : "r"(a[0]), "r"(a[1]), "r"(a[2]), "r"(a[3]), "r"(b[0]), "r"(b[1]));
}

// ---------------------------------------------------------------- merged prep
__global__ void prep_kernel(const float* __restrict__ x, const float* __restrict__ w) {
    if (blockIdx.x < PREP_X_BLOCKS) {
        int idx = (blockIdx.x * 256 + threadIdx.x) * 2;     // float4 index, 2 per thread
        #pragma unroll
        for (int q = 0; q < 2; q++) {
            float4 v = reinterpret_cast<const float4*>(x)[idx + q];
            __half2 h0 = __floats2half2_rn(v.x, v.y);
            __half2 h1 = __floats2half2_rn(v.z, v.w);
            uint2 u;
            u.x = *reinterpret_cast<uint32_t*>(&h0);
            u.y = *reinterpret_cast<uint32_t*>(&h1);
            reinterpret_cast<uint2*>(g_xh)[idx + q] = u;
        }
    } else {
        int blk  = blockIdx.x - PREP_X_BLOCKS;   // ck*32 + ntile
        int ck   = blk >> 5;
        int nt   = blk & 31;
        int tid  = threadIdx.x;                  // s2*128 + s1*64 + lane*2 + r
        int s2   = tid >> 7;
        int s1   = (tid >> 6) & 1;
        int lane = (tid >> 1) & 31;
        int r    = tid & 1;
        int g = lane >> 2, t = lane & 3;
        int n = nt * 8 + g;
        int k = ck * 64 + (s2 * 2 + s1) * 16 + r * 8 + t * 2;
        int p  = k >> 8;                         // tap (kh*3+kw)
        int ic = k & 255;
        float v0 = w[n * K_TOTAL + ic * (KH * KW) + p];
        float v1 = w[n * K_TOTAL + (ic + 1) * (KH * KW) + p];
        if (fabsf(v0) < SPARSE_TH) v0 = 0.0f;
        if (fabsf(v1) < SPARSE_TH) v1 = 0.0f;
        __half2 hv = __floats2half2_rn(v0, v1);
        g_Bpack[blk * 256 + tid] = *reinterpret_cast<uint32_t*>(&hv);
    }
}

// ---------------------------------------------------------------- main kernel
__global__ __launch_bounds__(THREADS, 3)
void conv_mma_kernel(const float* __restrict__ bias,
                     float* __restrict__ out) {
    extern __shared__ char smem[];
    const uint32_t sb = smem_u32(smem);

    const int tid    = threadIdx.x;
    const int lane   = tid & 31;
    const int wid    = tid >> 5;      // 0..3
    const int warp_m = wid & 1;       // 2 x 64 rows
    const int warp_n = wid >> 1;      // 2 x 64 cols
    const int g      = lane >> 2;
    const int t      = lane & 3;

    const int bm = blockIdx.y * BM;
    const int bn = blockIdx.x * BN;

    // de-lockstep the (up to) 3 co-resident CTAs
    const int phase = (blockIdx.y % 3) * (NUM_CHUNKS / 3);

    // ---- A cp.async: 1024 16B units/chunk, 8 per thread
    const int la_row = tid >> 3;      // 0..15 (+16*i)
    const int la_u   = tid & 7;       // 16B unit within row
    int rowbase[8];
    #pragma unroll
    for (int i = 0; i < 8; i++) {
        int m   = bm + la_row + 16 * i;
        int n   = m / (OH * OW);
        int rem = m - n * (OH * OW);
        int oh  = rem / OW;
        int ow  = rem - oh * OW;
        rowbase[i] = ((n * H_IN + oh) * W_IN + ow) * C_IN;
    }

    auto issue_copies = [&](int ck, int buf) {
        const int p   = ck >> 2;
        const int ic0 = (ck & 3) * 64;
        const int kh  = p / 3;
        const int kw  = p - kh * 3;
        const int aoff = (kh * W_IN + kw) * C_IN + ic0 + la_u * 8;
        const uint32_t aBase = sb + buf * STAGE_BYTES;
        #pragma unroll
        for (int i = 0; i < 8; i++) {
            const __half* src = g_xh + rowbase[i] + aoff;
            uint32_t off = (uint32_t)(la_row + 16 * i) * 128 + la_u * 16;
            off ^= (off >> 3) & 0x70;               // SW128
            asm volatile("cp.async.cg.shared.global [%0], [%1], 16;"
                         :: "r"(aBase + off), "l"(src) : "memory");
        }
        const uint32_t bBase = aBase + A_CHUNK_BYTES;
        const uint32_t* src = g_Bpack + (size_t)(ck * 32 + (bn >> 3)) * 256;
        #pragma unroll
        for (int ii = 0; ii < 8; ii++) {
            int idx = tid + THREADS * ii;           // 1024 16B units
            asm volatile("cp.async.cg.shared.global [%0], [%1], 16;"
                         :: "r"(bBase + idx * 16), "l"(src + idx * 4) : "memory");
        }
        asm volatile("cp.async.commit_group;" ::: "memory");
    };

    auto ckmap = [&](int cc) {
        int ck = cc + phase;
        return (ck >= NUM_CHUNKS) ? ck - NUM_CHUNKS : ck;
    };

    // ---- accumulators: 4 M-tiles x 8 N-tiles x 4 = 128 regs
    float acc[4][8][4];
    #pragma unroll
    for (int i = 0; i < 4; i++)
        #pragma unroll
        for (int j = 0; j < 8; j++)
            #pragma unroll
            for (int r = 0; r < 4; r++)
                acc[i][j][r] = 0.0f;

    // ---- prologue
    issue_copies(ckmap(0), 0);

    for (int cc = 0; cc < NUM_CHUNKS; cc++) {
        const int buf = cc & 1;

        __syncthreads();   // WAR: buf^1 free (compute(cc-1) done everywhere)

        if (cc + 1 < NUM_CHUNKS) {
            issue_copies(ckmap(cc + 1), buf ^ 1);
            asm volatile("cp.async.wait_group 1;" ::: "memory");   // chunk cc landed
        } else {
            asm volatile("cp.async.wait_group 0;" ::: "memory");
        }
        __syncthreads();

        // ---- compute chunk cc
        const uint32_t aBase = sb + buf * STAGE_BYTES;
        const uint32_t bBase = aBase + A_CHUNK_BYTES;

        #pragma unroll
        for (int s = 0; s < 4; s++) {
            uint32_t af[4][4];
            #pragma unroll
            for (int i = 0; i < 4; i++) {
                uint32_t off = (uint32_t)(warp_m * 64 + i * 16 + (lane & 15)) * 128
                             + s * 32 + (lane >> 4) * 16;
                off ^= (off >> 3) & 0x70;
                asm volatile(
                    "ldmatrix.sync.aligned.m8n8.x4.shared.b16 {%0,%1,%2,%3}, [%4];"
                    : "=r"(af[i][0]), "=r"(af[i][1]), "=r"(af[i][2]), "=r"(af[i][3])
                    : "r"(aBase + off));
            }
            #pragma unroll
            for (int j = 0; j < 8; j++) {
                const int lt = warp_n * 8 + j;     // ntile 0..15
                uint32_t bf[2];
                // conflict-free: lane stride 8B within a 256B block
                asm volatile("ld.shared.v2.b32 {%0,%1}, [%2];"
                             : "=r"(bf[0]), "=r"(bf[1])
                             : "r"(bBase + lt * 1024 + (s >> 1) * 512 + (s & 1) * 256 + lane * 8));
                #pragma unroll
                for (int i = 0; i < 4; i++)
                    mma_f16(acc[i][j], af[i], bf);
            }
        }
    }

    // ---- epilogue: registers -> gmem with bias
    #pragma unroll
    for (int j = 0; j < 8; j++) {
        const int n = bn + warp_n * 64 + j * 8 + t * 2;
        const float bvx = __ldg(bias + n);
        const float bvy = __ldg(bias + n + 1);
        #pragma unroll
        for (int i = 0; i < 4; i++) {
            const int m = bm + warp_m * 64 + i * 16 + g;
            float2 v0, v1;
            v0.x = acc[i][j][0] + bvx;
            v0.y = acc[i][j][1] + bvy;
            v1.x = acc[i][j][2] + bvx;
            v1.y = acc[i][j][3] + bvy;
            *reinterpret_cast<float2*>(out + (size_t)m * OC + n)       = v0;
            *reinterpret_cast<float2*>(out + (size_t)(m + 8) * OC + n) = v1;
        }
    }
}

// ---------------------------------------------------------------- launch
extern "C" void kernel_launch(void* const* d_in, const int* in_sizes, int n_in,
                              void* d_out, int out_size) {
    const float* x      = (const float*)d_in[0];
    const float* weight = (const float*)d_in[1];
    const float* bias   = (const float*)d_in[2];
    float*       out    = (float*)d_out;

    static bool attr_set = false;
    if (!attr_set) {
        cudaFuncSetAttribute(conv_mma_kernel,
                             cudaFuncAttributeMaxDynamicSharedMemorySize, SMEM_BYTES);
        attr_set = true;
    }

    prep_kernel<<<PREP_BLOCKS, 256>>>(x, weight);

    dim3 grid(OC / BN, M_TOTAL / BM);  // (2, 729)
    conv_mma_kernel<<<grid, THREADS, SMEM_BYTES>>>(bias, out);
}

// round 16
// speedup vs baseline: 1.1736x; 1.1736x over previous
#include <cuda_runtime.h>
#include <cuda_fp16.h>
#include <cstdint>

// ---------------------------------------------------------------- problem dims
constexpr int N_IN  = 32;
constexpr int H_IN  = 56;
constexpr int W_IN  = 56;
constexpr int C_IN  = 256;
constexpr int KH    = 3;
constexpr int KW    = 3;
constexpr int OC    = 256;
constexpr int OH    = 54;
constexpr int OW    = 54;

constexpr int M_TOTAL = N_IN * OH * OW;   // 93312
constexpr int K_TOTAL = KH * KW * C_IN;   // 2304
constexpr float SPARSE_TH = 0.01f;

// ---------------------------------------------------------------- GEMM config
constexpr int BM = 128;
constexpr int BN = 128;
constexpr int BK = 64;                       // 64 fp16 = 128B/row (SW128)
constexpr int NUM_CHUNKS = K_TOTAL / BK;     // 36
constexpr int X_ELEMS = N_IN * H_IN * W_IN * C_IN;  // 25690112

constexpr int THREADS = 128;                 // 4 warps, 2(M) x 2(N), warp tile 64x64

// smem: 3 stages, each A(16KB)+B(16KB); 96KB/CTA, 2 CTAs/SM
constexpr int A_CHUNK_BYTES = 16384;
constexpr int STAGE_BYTES   = 32768;
constexpr int NUM_STAGES    = 3;
constexpr int SMEM_BYTES    = NUM_STAGES * STAGE_BYTES;   // 98304

// fp16 image of x
__device__ __half g_xh[X_ELEMS];
// B pre-packed, conflict-free smem order:
// [ck][ntile 0..31][s2 0..1][s1 0..1][lane 0..31][r 0..1] (uint32 words)
// word(tid), tid = s2*128 + s1*64 + lane*2 + r
// word = half2 { B(k), B(k+1) }, k = ck*64 + (s2*2+s1)*16 + r*8 + t*2, n = ntile*8 + g
__device__ uint32_t g_Bpack[NUM_CHUNKS * 32 * 256];

// merged prep grid split: x part does 64B/thread (4 x float4)
constexpr int PREP_X_BLOCKS = X_ELEMS / 16 / 256;  // 6272 (64B/thread, exact)
constexpr int PREP_B_BLOCKS = NUM_CHUNKS * 32;     // 1152
constexpr int PREP_BLOCKS   = PREP_X_BLOCKS + PREP_B_BLOCKS;

__device__ __forceinline__ uint32_t smem_u32(const void* p) {
    uint32_t a;
    asm("{ .reg .u64 t; cvta.to.shared.u64 t, %1; cvt.u32.u64 %0, t; }" : "=r"(a) : "l"(p));
    return a;
}

__device__ __forceinline__ void mma_f16(float* c, const uint32_t* a, const uint32_t* b) {
    asm volatile(
        "mma.sync.aligned.m16n8k16.row.col.f32.f16.f16.f32 "
        "{%0,%1,%2,%3}, {%4,%5,%6,%7}, {%8,%9}, {%0,%1,%2,%3};"
        : "+f"(c[0]), "+f"(c[1]), "+f"(c[2]), "+f"(c[3])
        : "r"(a[0]), "r"(a[1]), "r"(a[2]), "r"(a[3]), "r"(b[0]), "r"(b[1]));
}

// ---------------------------------------------------------------- merged prep
__global__ void prep_kernel(const float* __restrict__ x, const float* __restrict__ w) {
    if (blockIdx.x < PREP_X_BLOCKS) {
        // x -> fp16, 64B per thread (4 float4 loads in flight)
        int idx = (blockIdx.x * 256 + threadIdx.x) * 4;     // float4 index
        float4 v0 = reinterpret_cast<const float4*>(x)[idx + 0];
        float4 v1 = reinterpret_cast<const float4*>(x)[idx + 1];
        float4 v2 = reinterpret_cast<const float4*>(x)[idx + 2];
        float4 v3 = reinterpret_cast<const float4*>(x)[idx + 3];
        uint4 o0, o1;
        {
            __half2 a = __floats2half2_rn(v0.x, v0.y), b = __floats2half2_rn(v0.z, v0.w);
            __half2 c = __floats2half2_rn(v1.x, v1.y), d = __floats2half2_rn(v1.z, v1.w);
            o0.x = *reinterpret_cast<uint32_t*>(&a); o0.y = *reinterpret_cast<uint32_t*>(&b);
            o0.z = *reinterpret_cast<uint32_t*>(&c); o0.w = *reinterpret_cast<uint32_t*>(&d);
        }
        {
            __half2 a = __floats2half2_rn(v2.x, v2.y), b = __floats2half2_rn(v2.z, v2.w);
            __half2 c = __floats2half2_rn(v3.x, v3.y), d = __floats2half2_rn(v3.z, v3.w);
            o1.x = *reinterpret_cast<uint32_t*>(&a); o1.y = *reinterpret_cast<uint32_t*>(&b);
            o1.z = *reinterpret_cast<uint32_t*>(&c); o1.w = *reinterpret_cast<uint32_t*>(&d);
        }
        reinterpret_cast<uint4*>(g_xh)[(idx >> 1) + 0] = o0;   // 2 float4 -> 1 uint4
        reinterpret_cast<uint4*>(g_xh)[(idx >> 1) + 1] = o1;
    } else {
        int blk  = blockIdx.x - PREP_X_BLOCKS;   // ck*32 + ntile
        int ck   = blk >> 5;
        int nt   = blk & 31;
        int tid  = threadIdx.x;                  // s2*128 + s1*64 + lane*2 + r
        int s2   = tid >> 7;
        int s1   = (tid >> 6) & 1;
        int lane = (tid >> 1) & 31;
        int r    = tid & 1;
        int g = lane >> 2, t = lane & 3;
        int n = nt * 8 + g;
        int k = ck * 64 + (s2 * 2 + s1) * 16 + r * 8 + t * 2;
        int p  = k >> 8;                         // tap (kh*3+kw)
        int ic = k & 255;
        float v0 = w[n * K_TOTAL + ic * (KH * KW) + p];
        float v1 = w[n * K_TOTAL + (ic + 1) * (KH * KW) + p];
        if (fabsf(v0) < SPARSE_TH) v0 = 0.0f;
        if (fabsf(v1) < SPARSE_TH) v1 = 0.0f;
        __half2 hv = __floats2half2_rn(v0, v1);
        g_Bpack[blk * 256 + tid] = *reinterpret_cast<uint32_t*>(&hv);
    }
}

// ---------------------------------------------------------------- main kernel
__global__ __launch_bounds__(THREADS, 2)
void conv_mma_kernel(const float* __restrict__ bias,
                     float* __restrict__ out) {
    extern __shared__ char smem[];
    const uint32_t sb = smem_u32(smem);

    const int tid    = threadIdx.x;
    const int lane   = tid & 31;
    const int wid    = tid >> 5;      // 0..3
    const int warp_m = wid & 1;       // 2 x 64 rows
    const int warp_n = wid >> 1;      // 2 x 64 cols
    const int g      = lane >> 2;
    const int t      = lane & 3;

    const int bm = blockIdx.y * BM;
    const int bn = blockIdx.x * BN;

    // de-lockstep co-resident CTA pairs
    const int phase = ((blockIdx.y / 74) & 1) * (NUM_CHUNKS / 2);

    // ---- A cp.async: 1024 16B units/chunk, 8 per thread
    const int la_row = tid >> 3;      // 0..15 (+16*i)
    const int la_u   = tid & 7;       // 16B unit within row
    int rowbase[8];
    #pragma unroll
    for (int i = 0; i < 8; i++) {
        int m   = bm + la_row + 16 * i;
        int n   = m / (OH * OW);
        int rem = m - n * (OH * OW);
        int oh  = rem / OW;
        int ow  = rem - oh * OW;
        rowbase[i] = ((n * H_IN + oh) * W_IN + ow) * C_IN;
    }

    auto issue_copies = [&](int ck, int stage) {
        const int p   = ck >> 2;
        const int ic0 = (ck & 3) * 64;
        const int kh  = p / 3;
        const int kw  = p - kh * 3;
        const int aoff = (kh * W_IN + kw) * C_IN + ic0 + la_u * 8;
        const uint32_t aBase = sb + stage * STAGE_BYTES;
        #pragma unroll
        for (int i = 0; i < 8; i++) {
            const __half* src = g_xh + rowbase[i] + aoff;
            uint32_t off = (uint32_t)(la_row + 16 * i) * 128 + la_u * 16;
            off ^= (off >> 3) & 0x70;               // SW128
            asm volatile("cp.async.cg.shared.global [%0], [%1], 16;"
                         :: "r"(aBase + off), "l"(src) : "memory");
        }
        const uint32_t bBase = aBase + A_CHUNK_BYTES;
        const uint32_t* src = g_Bpack + (size_t)(ck * 32 + (bn >> 3)) * 256;
        #pragma unroll
        for (int ii = 0; ii < 8; ii++) {
            int idx = tid + THREADS * ii;           // 1024 16B units
            asm volatile("cp.async.cg.shared.global [%0], [%1], 16;"
                         :: "r"(bBase + idx * 16), "l"(src + idx * 4) : "memory");
        }
        asm volatile("cp.async.commit_group;" ::: "memory");
    };

    auto ckmap = [&](int cc) {
        int ck = cc + phase;
        return (ck >= NUM_CHUNKS) ? ck - NUM_CHUNKS : ck;
    };

    // ---- accumulators: 4 M-tiles x 8 N-tiles x 4 = 128 regs
    float acc[4][8][4];
    #pragma unroll
    for (int i = 0; i < 4; i++)
        #pragma unroll
        for (int j = 0; j < 8; j++)
            #pragma unroll
            for (int r = 0; r < 4; r++)
                acc[i][j][r] = 0.0f;

    // ---- prologue: stages 0,1
    issue_copies(ckmap(0), 0);
    issue_copies(ckmap(1), 1);

    int cstage = 0;   // stage holding chunk cc
    int istage = 2;   // stage to fill with chunk cc+2

    for (int cc = 0; cc < NUM_CHUNKS; cc++) {
        if (cc < NUM_CHUNKS - 1) {
            asm volatile("cp.async.wait_group 1;" ::: "memory");
        } else {
            asm volatile("cp.async.wait_group 0;" ::: "memory");
        }
        __syncthreads();   // copy visibility + WAR vs compute(cc-1)

        const uint32_t aBase = sb + cstage * STAGE_BYTES;
        const uint32_t bBase = aBase + A_CHUNK_BYTES;

        // 1) hoist all A-fragment ldmatrix FIRST (critical path for the MMAs)
        uint32_t af[4][4][4];   // [s][i][frag]
        #pragma unroll
        for (int s = 0; s < 4; s++) {
            #pragma unroll
            for (int i = 0; i < 4; i++) {
                uint32_t off = (uint32_t)(warp_m * 64 + i * 16 + (lane & 15)) * 128
                             + s * 32 + (lane >> 4) * 16;
                off ^= (off >> 3) & 0x70;
                asm volatile(
                    "ldmatrix.sync.aligned.m8n8.x4.shared.b16 {%0,%1,%2,%3}, [%4];"
                    : "=r"(af[s][i][0]), "=r"(af[s][i][1]),
                      "=r"(af[s][i][2]), "=r"(af[s][i][3])
                    : "r"(aBase + off));
            }
        }

        // 2) THEN issue next-next chunk's copies (no urgency; fills LSU while
        //    ldmatrix results are in flight and MMAs drain)
        if (cc + 2 < NUM_CHUNKS) issue_copies(ckmap(cc + 2), istage);

        // 3) MMA stream
        #pragma unroll
        for (int s = 0; s < 4; s++) {
            #pragma unroll
            for (int j = 0; j < 8; j++) {
                const int lt = warp_n * 8 + j;     // ntile 0..15
                uint32_t bf[2];
                // conflict-free: lane stride 8B within a 256B block
                asm volatile("ld.shared.v2.b32 {%0,%1}, [%2];"
                             : "=r"(bf[0]), "=r"(bf[1])
                             : "r"(bBase + lt * 1024 + (s >> 1) * 512 + (s & 1) * 256 + lane * 8));
                #pragma unroll
                for (int i = 0; i < 4; i++)
                    mma_f16(acc[i][j], af[s][i], bf);
            }
        }

        cstage = (cstage == NUM_STAGES - 1) ? 0 : cstage + 1;
        istage = (istage == NUM_STAGES - 1) ? 0 : istage + 1;
    }

    // ---- epilogue: registers -> gmem with bias
    #pragma unroll
    for (int j = 0; j < 8; j++) {
        const int n = bn + warp_n * 64 + j * 8 + t * 2;
        const float bvx = __ldg(bias + n);
        const float bvy = __ldg(bias + n + 1);
        #pragma unroll
        for (int i = 0; i < 4; i++) {
            const int m = bm + warp_m * 64 + i * 16 + g;
            float2 v0, v1;
            v0.x = acc[i][j][0] + bvx;
            v0.y = acc[i][j][1] + bvy;
            v1.x = acc[i][j][2] + bvx;
            v1.y = acc[i][j][3] + bvy;
            *reinterpret_cast<float2*>(out + (size_t)m * OC + n)       = v0;
            *reinterpret_cast<float2*>(out + (size_t)(m + 8) * OC + n) = v1;
        }
    }
}

// ---------------------------------------------------------------- launch
extern "C" void kernel_launch(void* const* d_in, const int* in_sizes, int n_in,
                              void* d_out, int out_size) {
    const float* x      = (const float*)d_in[0];
    const float* weight = (const float*)d_in[1];
    const float* bias   = (const float*)d_in[2];
    float*       out    = (float*)d_out;

    static bool attr_set = false;
    if (!attr_set) {
        cudaFuncSetAttribute(conv_mma_kernel,
                             cudaFuncAttributeMaxDynamicSharedMemorySize, SMEM_BYTES);
        attr_set = true;
    }

    prep_kernel<<<PREP_BLOCKS, 256>>>(x, weight);

    dim3 grid(OC / BN, M_TOTAL / BM);  // (2, 729)
    conv_mma_kernel<<<grid, THREADS, SMEM_BYTES>>>(bias, out);
}